// round 4
// baseline (speedup 1.0000x reference)
#include <cuda_runtime.h>
#include <mma.h>
#include <cstdint>

using namespace nvcuda;

#define NPOINTS   262144
#define NNET      512
#define IN_F      256
#define OUT_F     256
#define BM        128
#define BN        128
#define BK        32
#define N_CHUNKS  (IN_F / BK)        /* 8 */
#define SUBTILES  6                  /* ceil(768/128) */
#define NCOLS     (OUT_F / BN)       /* 2 */
#define THREADS   256

// SMEM strides (floats), padded for bank-conflict-free wmma loads (16B-multiple ldm)
#define LDA   36    /* 32 + 4 */
#define LDB   132   /* 128 + 4 */
#define LDE   132   /* epilogue buffer stride */

// byte offsets in dynamic SMEM
#define A_BYTES   (BM * LDA * 4)                 /* 18432 */
#define B_BYTES   (BK * LDB * 4)                 /* 16896 */
#define STAGE     (A_BYTES + B_BYTES)            /* 35328, multiple of 128 */
#define SMEM_TOTAL (2 * STAGE)                   /* 70656; epi (128*132*4=67584) reuses it */

__device__ int g_seg[NNET];   // start point index per network

// ---------------- cp.async helpers (baseline sm_80+ PTX, valid on compute_103) ----------------
__device__ __forceinline__ uint32_t smem_u32(const void* p) {
    uint32_t a;
    asm("{ .reg .u64 t; cvta.to.shared.u64 t, %1; cvt.u32.u64 %0, t; }" : "=r"(a) : "l"(p));
    return a;
}
__device__ __forceinline__ void cp_async16(uint32_t dst, const void* src, bool valid) {
    int sz = valid ? 16 : 0;   // ignore-src: bytes beyond src-size are zero-filled
    asm volatile("cp.async.cg.shared.global [%0], [%1], 16, %2;"
                 :: "r"(dst), "l"(src), "r"(sz));
}
__device__ __forceinline__ void cp_commit() {
    asm volatile("cp.async.commit_group;" ::: "memory");
}
template <int N>
__device__ __forceinline__ void cp_wait() {
    asm volatile("cp.async.wait_group %0;" :: "n"(N) : "memory");
}

// ---------------- kernel 1: segment starts ----------------
__global__ void seg_kernel(const int* __restrict__ net_id) {
    int p = blockIdx.x * blockDim.x + threadIdx.x;
    if (p >= NPOINTS) return;
    int nid = net_id[p];
    if (p == 0 || net_id[p - 1] != nid) g_seg[nid] = p;
}

// ---------------- kernel 2: grouped GEMM (wmma tf32, 2-stage cp.async pipeline) -------------
__global__ void __launch_bounds__(THREADS)
grouped_gemm_kernel(const float* __restrict__ x, const float* __restrict__ weight,
                    const float* __restrict__ bias, float* __restrict__ out) {
    // decode: ncol fastest, then subtile, then network (same-network CTAs adjacent for L2 W reuse)
    int bx   = blockIdx.x;
    int ncol = bx & (NCOLS - 1);
    int sub  = (bx >> 1) % SUBTILES;
    int n    = bx / (SUBTILES * NCOLS);

    int s0 = g_seg[n];
    int s1 = (n == NNET - 1) ? NPOINTS : g_seg[n + 1];
    int row0 = s0 + sub * BM;
    int cnt = s1 - row0;
    if (cnt <= 0) return;                 // empty sub-tile: whole CTA exits
    if (cnt > BM) cnt = BM;
    int ncol0 = ncol * BN;

    extern __shared__ char smem[];
    float* smf = reinterpret_cast<float*>(smem);
    uint32_t smem_base = smem_u32(smem);

    int tid = threadIdx.x;
    int wid = tid >> 5;
    int warp_m = wid >> 2;                // 0..1 -> 64-row slab
    int warp_n = wid & 3;                 // 0..3 -> 32-col slab

    const float* wsrc = weight + (size_t)n * IN_F * OUT_F;   // [in][out], out contiguous = row-major KxN

    // per-thread load coordinates (fixed across chunks)
    // A tile: 128 rows x 8 float4  -> 1024 float4, 4 per thread
    int ar[4], ac[4]; bool av[4]; uint32_t adst[4];
    // B tile: 32 rows x 32 float4  -> 1024 float4, 4 per thread
    int br[4], bc[4]; uint32_t bdst[4];
#pragma unroll
    for (int j = 0; j < 4; j++) {
        int idx = tid + j * THREADS;
        ar[j] = idx >> 3; ac[j] = idx & 7;
        av[j] = ar[j] < cnt;
        adst[j] = (uint32_t)(ar[j] * LDA * 4 + ac[j] * 16);
        br[j] = idx >> 5; bc[j] = idx & 31;
        bdst[j] = (uint32_t)(A_BYTES + br[j] * LDB * 4 + bc[j] * 16);
    }

    // pipeline: issue chunk 0
    {
        const float* xs = x + (size_t)row0 * IN_F;   // + r*IN_F + c8*4
#pragma unroll
        for (int j = 0; j < 4; j++)
            cp_async16(smem_base + adst[j],
                       xs + (size_t)(av[j] ? ar[j] : 0) * IN_F + ac[j] * 4, av[j]);
#pragma unroll
        for (int j = 0; j < 4; j++)
            cp_async16(smem_base + bdst[j],
                       wsrc + (size_t)br[j] * OUT_F + ncol0 + bc[j] * 4, true);
        cp_commit();
    }

    wmma::fragment<wmma::accumulator, 16, 16, 8, float> acc[4][2];
#pragma unroll
    for (int mt = 0; mt < 4; mt++)
#pragma unroll
        for (int nt = 0; nt < 2; nt++)
            wmma::fill_fragment(acc[mt][nt], 0.0f);

    for (int c = 0; c < N_CHUNKS; c++) {
        int buf = c & 1;
        // issue next chunk into the other buffer
        if (c + 1 < N_CHUNKS) {
            int nbuf = (c + 1) & 1;
            int k0 = (c + 1) * BK;
            const float* xs = x + (size_t)row0 * IN_F + k0;
#pragma unroll
            for (int j = 0; j < 4; j++)
                cp_async16(smem_base + nbuf * STAGE + adst[j],
                           xs + (size_t)(av[j] ? ar[j] : 0) * IN_F + ac[j] * 4, av[j]);
#pragma unroll
            for (int j = 0; j < 4; j++)
                cp_async16(smem_base + nbuf * STAGE + bdst[j],
                           wsrc + (size_t)(k0 + br[j]) * OUT_F + ncol0 + bc[j] * 4, true);
            cp_commit();
            cp_wait<1>();
        } else {
            cp_wait<0>();
        }
        __syncthreads();

        const float* As = smf + buf * (STAGE / 4);
        const float* Bs = smf + buf * (STAGE / 4) + (A_BYTES / 4);

#pragma unroll
        for (int ks = 0; ks < 4; ks++) {
            int k0 = ks * 8;
            wmma::fragment<wmma::matrix_a, 16, 16, 8, wmma::precision::tf32, wmma::row_major> af[4];
            wmma::fragment<wmma::matrix_b, 16, 16, 8, wmma::precision::tf32, wmma::row_major> bf[2];
#pragma unroll
            for (int mt = 0; mt < 4; mt++) {
                wmma::load_matrix_sync(af[mt], As + (warp_m * 64 + mt * 16) * LDA + k0, LDA);
#pragma unroll
                for (int t = 0; t < af[mt].num_elements; t++)
                    af[mt].x[t] = wmma::__float_to_tf32(af[mt].x[t]);
            }
#pragma unroll
            for (int nt = 0; nt < 2; nt++) {
                wmma::load_matrix_sync(bf[nt], Bs + k0 * LDB + warp_n * 32 + nt * 16, LDB);
#pragma unroll
                for (int t = 0; t < bf[nt].num_elements; t++)
                    bf[nt].x[t] = wmma::__float_to_tf32(bf[nt].x[t]);
            }
#pragma unroll
            for (int mt = 0; mt < 4; mt++)
#pragma unroll
                for (int nt = 0; nt < 2; nt++)
                    wmma::mma_sync(acc[mt][nt], af[mt], bf[nt], acc[mt][nt]);
        }
        __syncthreads();
    }

    // ---- epilogue: accum -> SMEM (padded), then coalesced gmem stores with bias add ----
#pragma unroll
    for (int mt = 0; mt < 4; mt++)
#pragma unroll
        for (int nt = 0; nt < 2; nt++)
            wmma::store_matrix_sync(
                smf + (warp_m * 64 + mt * 16) * LDE + warp_n * 32 + nt * 16,
                acc[mt][nt], LDE, wmma::mem_row_major);
    __syncthreads();

    int c4 = tid & 31;                    // fixed float4 column per thread
    int rb = tid >> 5;                    // base row, stride 8
    float4 bv = *reinterpret_cast<const float4*>(bias + (size_t)n * OUT_F + ncol0 + c4 * 4);
#pragma unroll
    for (int i = 0; i < 16; i++) {
        int r = rb + i * 8;
        if (r < cnt) {
            float4 v = *reinterpret_cast<const float4*>(smf + r * LDE + c4 * 4);
            v.x += bv.x; v.y += bv.y; v.z += bv.z; v.w += bv.w;
            *reinterpret_cast<float4*>(out + (size_t)(row0 + r) * OUT_F + ncol0 + c4 * 4) = v;
        }
    }
}

// ---------------- launcher ----------------
extern "C" void kernel_launch(void* const* d_in, const int* in_sizes, int n_in,
                              void* d_out, int out_size) {
    const float* x      = (const float*)d_in[0];
    const float* weight = (const float*)d_in[1];
    const float* bias   = (const float*)d_in[2];
    const int*   net_id = (const int*)d_in[3];
    // d_in[4] = slot_id (unused: points are sorted, slots contiguous within segments)
    float* out = (float*)d_out;

    cudaFuncSetAttribute(grouped_gemm_kernel,
                         cudaFuncAttributeMaxDynamicSharedMemorySize, SMEM_TOTAL);

    seg_kernel<<<NPOINTS / 256, 256>>>(net_id);
    grouped_gemm_kernel<<<NNET * SUBTILES * NCOLS, THREADS, SMEM_TOTAL>>>(x, weight, bias, out);
}

// round 5
// speedup vs baseline: 1.1250x; 1.1250x over previous
#include <cuda_runtime.h>
#include <mma.h>
#include <cstdint>

using namespace nvcuda;

#define NPOINTS   262144
#define NNET      512
#define IN_F      256
#define OUT_F     256
#define BM        128
#define BN        128
#define BK        32
#define N_CHUNKS  (IN_F / BK)        /* 8 */
#define SUBTILES  6                  /* ceil(768/128) */
#define NCOLS     (OUT_F / BN)       /* 2 */
#define THREADS   256

// SMEM strides (floats), padded for bank-conflict-free wmma loads (16B-multiple ldm)
#define LDA   36    /* 32 + 4 */
#define LDB   132   /* 128 + 4 */
#define LDE   132   /* epilogue buffer stride */

// byte offsets in dynamic SMEM
#define A_BYTES   (BM * LDA * 4)                 /* 18432 */
#define B_BYTES   (BK * LDB * 4)                 /* 16896 */
#define STAGE     (A_BYTES + B_BYTES)            /* 35328, multiple of 128 */
#define SMEM_TOTAL (2 * STAGE)                   /* 70656; epi (128*132*4=67584) reuses it */

__device__ int g_seg[NNET];   // start point index per network

// ---------------- cp.async helpers (baseline sm_80+ PTX, valid on compute_103) ----------------
__device__ __forceinline__ uint32_t smem_u32(const void* p) {
    uint32_t a;
    asm("{ .reg .u64 t; cvta.to.shared.u64 t, %1; cvt.u32.u64 %0, t; }" : "=r"(a) : "l"(p));
    return a;
}
__device__ __forceinline__ void cp_async16(uint32_t dst, const void* src, bool valid) {
    int sz = valid ? 16 : 0;   // ignore-src: bytes beyond src-size are zero-filled
    asm volatile("cp.async.cg.shared.global [%0], [%1], 16, %2;"
                 :: "r"(dst), "l"(src), "r"(sz));
}
__device__ __forceinline__ void cp_commit() {
    asm volatile("cp.async.commit_group;" ::: "memory");
}
template <int N>
__device__ __forceinline__ void cp_wait() {
    asm volatile("cp.async.wait_group %0;" :: "n"(N) : "memory");
}

// ---------------- kernel 1: segment starts ----------------
__global__ void seg_kernel(const int* __restrict__ net_id) {
    int p = blockIdx.x * blockDim.x + threadIdx.x;
    if (p >= NPOINTS) return;
    int nid = net_id[p];
    if (p == 0 || net_id[p - 1] != nid) g_seg[nid] = p;
}

// ---------------- kernel 2: grouped GEMM (wmma tf32, 2-stage cp.async, 2 CTAs/SM) -----------
__global__ void __launch_bounds__(THREADS, 2)
grouped_gemm_kernel(const float* __restrict__ x, const float* __restrict__ weight,
                    const float* __restrict__ bias, float* __restrict__ out) {
    // decode: ncol fastest, then subtile, then network (same-network CTAs adjacent for L2 W reuse)
    int bx   = blockIdx.x;
    int ncol = bx & (NCOLS - 1);
    int sub  = (bx >> 1) % SUBTILES;
    int n    = bx / (SUBTILES * NCOLS);

    int s0 = g_seg[n];
    int s1 = (n == NNET - 1) ? NPOINTS : g_seg[n + 1];
    int row0 = s0 + sub * BM;
    int cnt = s1 - row0;
    if (cnt <= 0) return;                 // empty sub-tile: whole CTA exits
    if (cnt > BM) cnt = BM;
    int ncol0 = ncol * BN;

    extern __shared__ char smem[];
    float* smf = reinterpret_cast<float*>(smem);
    uint32_t smem_base = smem_u32(smem);

    int tid = threadIdx.x;
    int wid = tid >> 5;
    int warp_m = wid >> 2;                // 0..1 -> 64-row slab
    int warp_n = wid & 3;                 // 0..3 -> 32-col slab

    const float* wsrc = weight + (size_t)n * IN_F * OUT_F;   // [in][out]: row-major KxN

    // per-thread load coordinates (fixed across chunks)
    int ar[4], ac[4]; bool av[4]; uint32_t adst[4];
    int br[4], bc[4]; uint32_t bdst[4];
#pragma unroll
    for (int j = 0; j < 4; j++) {
        int idx = tid + j * THREADS;
        ar[j] = idx >> 3; ac[j] = idx & 7;
        av[j] = ar[j] < cnt;
        adst[j] = (uint32_t)(ar[j] * LDA * 4 + ac[j] * 16);
        br[j] = idx >> 5; bc[j] = idx & 31;
        bdst[j] = (uint32_t)(A_BYTES + br[j] * LDB * 4 + bc[j] * 16);
    }

    // pipeline: issue chunk 0
    {
        const float* xs = x + (size_t)row0 * IN_F;
#pragma unroll
        for (int j = 0; j < 4; j++)
            cp_async16(smem_base + adst[j],
                       xs + (size_t)(av[j] ? ar[j] : 0) * IN_F + ac[j] * 4, av[j]);
#pragma unroll
        for (int j = 0; j < 4; j++)
            cp_async16(smem_base + bdst[j],
                       wsrc + (size_t)br[j] * OUT_F + ncol0 + bc[j] * 4, true);
        cp_commit();
    }

    wmma::fragment<wmma::accumulator, 16, 16, 8, float> acc[4][2];
#pragma unroll
    for (int mt = 0; mt < 4; mt++)
#pragma unroll
        for (int nt = 0; nt < 2; nt++)
            wmma::fill_fragment(acc[mt][nt], 0.0f);

    for (int c = 0; c < N_CHUNKS; c++) {
        int buf = c & 1;
        if (c + 1 < N_CHUNKS) {
            int nbuf = (c + 1) & 1;
            int k0 = (c + 1) * BK;
            const float* xs = x + (size_t)row0 * IN_F + k0;
#pragma unroll
            for (int j = 0; j < 4; j++)
                cp_async16(smem_base + nbuf * STAGE + adst[j],
                           xs + (size_t)(av[j] ? ar[j] : 0) * IN_F + ac[j] * 4, av[j]);
#pragma unroll
            for (int j = 0; j < 4; j++)
                cp_async16(smem_base + nbuf * STAGE + bdst[j],
                           wsrc + (size_t)(k0 + br[j]) * OUT_F + ncol0 + bc[j] * 4, true);
            cp_commit();
            cp_wait<1>();
        } else {
            cp_wait<0>();
        }
        __syncthreads();

        const float* As = smf + buf * (STAGE / 4);
        const float* Bs = smf + buf * (STAGE / 4) + (A_BYTES / 4);

#pragma unroll
        for (int ks = 0; ks < 4; ks++) {
            int k0 = ks * 8;
            // hold only bf[2] (8 regs) live; stream af one at a time (4 regs)
            wmma::fragment<wmma::matrix_b, 16, 16, 8, wmma::precision::tf32, wmma::row_major> bf[2];
#pragma unroll
            for (int nt = 0; nt < 2; nt++) {
                wmma::load_matrix_sync(bf[nt], Bs + k0 * LDB + warp_n * 32 + nt * 16, LDB);
#pragma unroll
                for (int t = 0; t < bf[nt].num_elements; t++)
                    bf[nt].x[t] = wmma::__float_to_tf32(bf[nt].x[t]);
            }
#pragma unroll
            for (int mt = 0; mt < 4; mt++) {
                wmma::fragment<wmma::matrix_a, 16, 16, 8, wmma::precision::tf32, wmma::row_major> af;
                wmma::load_matrix_sync(af, As + (warp_m * 64 + mt * 16) * LDA + k0, LDA);
#pragma unroll
                for (int t = 0; t < af.num_elements; t++)
                    af.x[t] = wmma::__float_to_tf32(af.x[t]);
                wmma::mma_sync(acc[mt][0], af, bf[0], acc[mt][0]);
                wmma::mma_sync(acc[mt][1], af, bf[1], acc[mt][1]);
            }
        }
        __syncthreads();
    }

    // ---- epilogue: accum -> SMEM (padded), then coalesced gmem stores with bias add ----
#pragma unroll
    for (int mt = 0; mt < 4; mt++)
#pragma unroll
        for (int nt = 0; nt < 2; nt++)
            wmma::store_matrix_sync(
                smf + (warp_m * 64 + mt * 16) * LDE + warp_n * 32 + nt * 16,
                acc[mt][nt], LDE, wmma::mem_row_major);
    __syncthreads();

    int c4 = tid & 31;                    // fixed float4 column per thread
    int rb = tid >> 5;                    // base row, stride 8
    float4 bv = *reinterpret_cast<const float4*>(bias + (size_t)n * OUT_F + ncol0 + c4 * 4);
#pragma unroll
    for (int i = 0; i < 16; i++) {
        int r = rb + i * 8;
        if (r < cnt) {
            float4 v = *reinterpret_cast<const float4*>(smf + r * LDE + c4 * 4);
            v.x += bv.x; v.y += bv.y; v.z += bv.z; v.w += bv.w;
            *reinterpret_cast<float4*>(out + (size_t)(row0 + r) * OUT_F + ncol0 + c4 * 4) = v;
        }
    }
}

// ---------------- launcher ----------------
extern "C" void kernel_launch(void* const* d_in, const int* in_sizes, int n_in,
                              void* d_out, int out_size) {
    const float* x      = (const float*)d_in[0];
    const float* weight = (const float*)d_in[1];
    const float* bias   = (const float*)d_in[2];
    const int*   net_id = (const int*)d_in[3];
    // d_in[4] = slot_id (unused: points are sorted, slots contiguous within segments)
    float* out = (float*)d_out;

    cudaFuncSetAttribute(grouped_gemm_kernel,
                         cudaFuncAttributeMaxDynamicSharedMemorySize, SMEM_TOTAL);

    seg_kernel<<<NPOINTS / 256, 256>>>(net_id);
    grouped_gemm_kernel<<<NNET * SUBTILES * NCOLS, THREADS, SMEM_TOTAL>>>(x, weight, bias, out);
}

// round 6
// speedup vs baseline: 1.9755x; 1.7559x over previous
#include <cuda_runtime.h>
#include <cuda_fp16.h>
#include <mma.h>
#include <cstdint>
#include <cstring>

using namespace nvcuda;

#define NPOINTS   262144
#define NNET      512
#define IN_F      256
#define OUT_F     256
#define BM        128
#define BN        128
#define BK        32
#define N_CHUNKS  (IN_F / BK)        /* 8 */
#define SUBTILES  6                  /* ceil(768/128) */
#define NCOLS     (OUT_F / BN)       /* 2 */
#define THREADS   256

// fp16 tile strides (halves), padded so LDSM phases hit distinct banks
#define LDAH  40    /* 32 + 8 */
#define LDBH  136   /* 128 + 8 */
#define LDE   132   /* fp32 epilogue buffer stride */

// ---- dynamic SMEM layout (bytes) ----
// fp32 staging (double buffered) then fp16 tiles (single buffered)
#define A32S      (BM * BK * 4)                  /* 16384 */
#define B32S      (BK * BN * 4)                  /* 16384 */
#define A32_OFF   0                              /* + buf*A32S, 2 bufs */
#define B32_OFF   (2 * A32S)                     /* + buf*B32S, 2 bufs */
#define AH_OFF    (B32_OFF + 2 * B32S)           /* 65536 */
#define AH_BYTES  (BM * LDAH * 2)                /* 10240 */
#define BH_OFF    (AH_OFF + AH_BYTES)            /* 75776 */
#define BH_BYTES  (BK * LDBH * 2)                /* 8704 */
#define SMEM_TOTAL (BH_OFF + BH_BYTES)           /* 84480; epi (67584) reuses it */

__device__ int g_seg[NNET];   // start point index per network

// ---------------- helpers ----------------
__device__ __forceinline__ uint32_t smem_u32(const void* p) {
    uint32_t a;
    asm("{ .reg .u64 t; cvta.to.shared.u64 t, %1; cvt.u32.u64 %0, t; }" : "=r"(a) : "l"(p));
    return a;
}
__device__ __forceinline__ void cp_async16(uint32_t dst, const void* src, bool valid) {
    int sz = valid ? 16 : 0;   // ignore-src: bytes beyond src-size are zero-filled
    asm volatile("cp.async.cg.shared.global [%0], [%1], 16, %2;"
                 :: "r"(dst), "l"(src), "r"(sz));
}
__device__ __forceinline__ void cp_commit() {
    asm volatile("cp.async.commit_group;" ::: "memory");
}
template <int N>
__device__ __forceinline__ void cp_wait() {
    asm volatile("cp.async.wait_group %0;" :: "n"(N) : "memory");
}
__device__ __forceinline__ uint32_t h2u(__half2 h) {
    uint32_t u; memcpy(&u, &h, 4); return u;
}

// ---------------- kernel 1: segment starts ----------------
__global__ void seg_kernel(const int* __restrict__ net_id) {
    int p = blockIdx.x * blockDim.x + threadIdx.x;
    if (p >= NPOINTS) return;
    int nid = net_id[p];
    if (p == 0 || net_id[p - 1] != nid) g_seg[nid] = p;
}

// -------- kernel 2: grouped GEMM (fp16 HMMA m16n16k16, fp32 accum, 2 CTAs/SM) --------
__global__ void __launch_bounds__(THREADS, 2)
grouped_gemm_kernel(const float* __restrict__ x, const float* __restrict__ weight,
                    const float* __restrict__ bias, float* __restrict__ out) {
    // decode: ncol fastest, then subtile, then network (same-network CTAs adjacent for L2 W reuse)
    int bx   = blockIdx.x;
    int ncol = bx & (NCOLS - 1);
    int sub  = (bx >> 1) % SUBTILES;
    int n    = bx / (SUBTILES * NCOLS);

    int s0 = g_seg[n];
    int s1 = (n == NNET - 1) ? NPOINTS : g_seg[n + 1];
    int row0 = s0 + sub * BM;
    int cnt = s1 - row0;
    if (cnt <= 0) return;                 // empty sub-tile: whole CTA exits
    if (cnt > BM) cnt = BM;
    int ncol0 = ncol * BN;

    extern __shared__ char smem[];
    float* smf = reinterpret_cast<float*>(smem);
    uint32_t smem_base = smem_u32(smem);

    int tid = threadIdx.x;
    int wid = tid >> 5;
    int warp_m = wid >> 2;                // 0..1 -> 64-row slab
    int warp_n = wid & 3;                 // 0..3 -> 32-col slab

    const float* wsrc = weight + (size_t)n * IN_F * OUT_F;   // [in][out]: row-major KxN

    // cp.async coordinates (fp32 staging, unpadded)
    int ar[4], ac[4]; bool av[4]; uint32_t adst[4];
    int br[4], bc[4]; uint32_t bdst[4];
#pragma unroll
    for (int j = 0; j < 4; j++) {
        int idx = tid + j * THREADS;
        ar[j] = idx >> 3; ac[j] = idx & 7;          // A: 128 rows x 8 float4
        av[j] = ar[j] < cnt;
        adst[j] = (uint32_t)(A32_OFF + ar[j] * BK * 4 + ac[j] * 16);
        br[j] = idx >> 5; bc[j] = idx & 31;          // B: 32 rows x 32 float4
        bdst[j] = (uint32_t)(B32_OFF + br[j] * BN * 4 + bc[j] * 16);
    }

    // convert-pass coordinates
    int car = tid >> 1, cac = (tid & 1) * 16;        // A: thread -> (row, 16-float half-row)
    int cbr = tid >> 3, cbc = (tid & 7) * 16;        // B: thread -> (row, 16-float span)
    const float* a32_t0 = smf + (A32_OFF >> 2) + car * BK + cac;
    const float* b32_t0 = smf + (B32_OFF >> 2) + cbr * BN + cbc;
    uint32_t* ah_dst = reinterpret_cast<uint32_t*>(smem + AH_OFF + (car * LDAH + cac) * 2);
    uint32_t* bh_dst = reinterpret_cast<uint32_t*>(smem + BH_OFF + (cbr * LDBH + cbc) * 2);
    const __half* Ah = reinterpret_cast<const __half*>(smem + AH_OFF);
    const __half* Bh = reinterpret_cast<const __half*>(smem + BH_OFF);

    // prologue: issue chunk 0
    {
        const float* xs = x + (size_t)row0 * IN_F;
#pragma unroll
        for (int j = 0; j < 4; j++)
            cp_async16(smem_base + adst[j],
                       xs + (size_t)(av[j] ? ar[j] : 0) * IN_F + ac[j] * 4, av[j]);
#pragma unroll
        for (int j = 0; j < 4; j++)
            cp_async16(smem_base + bdst[j],
                       wsrc + (size_t)br[j] * OUT_F + ncol0 + bc[j] * 4, true);
        cp_commit();
    }

    wmma::fragment<wmma::accumulator, 16, 16, 16, float> acc[4][2];
#pragma unroll
    for (int mt = 0; mt < 4; mt++)
#pragma unroll
        for (int nt = 0; nt < 2; nt++)
            wmma::fill_fragment(acc[mt][nt], 0.0f);

    for (int c = 0; c < N_CHUNKS; c++) {
        int buf = c & 1;
        if (c + 1 < N_CHUNKS) {
            int nbuf = (c + 1) & 1;
            int k0 = (c + 1) * BK;
            const float* xs = x + (size_t)row0 * IN_F + k0;
#pragma unroll
            for (int j = 0; j < 4; j++)
                cp_async16(smem_base + nbuf * A32S + adst[j],
                           xs + (size_t)(av[j] ? ar[j] : 0) * IN_F + ac[j] * 4, av[j]);
#pragma unroll
            for (int j = 0; j < 4; j++)
                cp_async16(smem_base + nbuf * B32S + bdst[j],
                           wsrc + (size_t)(k0 + br[j]) * OUT_F + ncol0 + bc[j] * 4, true);
            cp_commit();
            cp_wait<1>();
        } else {
            cp_wait<0>();
        }
        __syncthreads();   // staging(c) ready AND all warps finished mma(c-1) on fp16 tiles

        // ---- convert pass: fp32 staging(buf) -> fp16 tiles (16 cvt + 4 STS.128 / thread) ----
        {
            const float* a32 = a32_t0 + buf * (A32S >> 2);
            const float* b32 = b32_t0 + buf * (B32S >> 2);
            float4 va[4], vb[4];
#pragma unroll
            for (int j = 0; j < 4; j++) va[j] = *reinterpret_cast<const float4*>(a32 + j * 4);
#pragma unroll
            for (int j = 0; j < 4; j++) vb[j] = *reinterpret_cast<const float4*>(b32 + j * 4);
            uint4 pa[2], pb[2];
#pragma unroll
            for (int j = 0; j < 2; j++) {
                pa[j].x = h2u(__float22half2_rn(make_float2(va[2*j].x,   va[2*j].y)));
                pa[j].y = h2u(__float22half2_rn(make_float2(va[2*j].z,   va[2*j].w)));
                pa[j].z = h2u(__float22half2_rn(make_float2(va[2*j+1].x, va[2*j+1].y)));
                pa[j].w = h2u(__float22half2_rn(make_float2(va[2*j+1].z, va[2*j+1].w)));
                pb[j].x = h2u(__float22half2_rn(make_float2(vb[2*j].x,   vb[2*j].y)));
                pb[j].y = h2u(__float22half2_rn(make_float2(vb[2*j].z,   vb[2*j].w)));
                pb[j].z = h2u(__float22half2_rn(make_float2(vb[2*j+1].x, vb[2*j+1].y)));
                pb[j].w = h2u(__float22half2_rn(make_float2(vb[2*j+1].z, vb[2*j+1].w)));
            }
            *reinterpret_cast<uint4*>(ah_dst)     = pa[0];
            *reinterpret_cast<uint4*>(ah_dst + 4) = pa[1];
            *reinterpret_cast<uint4*>(bh_dst)     = pb[0];
            *reinterpret_cast<uint4*>(bh_dst + 4) = pb[1];
        }
        __syncthreads();   // fp16 tiles ready

        // ---- MMA: 2 k-steps of m16n16k16, LDSM fragment loads, no cvt ----
#pragma unroll
        for (int ks = 0; ks < 2; ks++) {
            int k0 = ks * 16;
            wmma::fragment<wmma::matrix_b, 16, 16, 16, __half, wmma::row_major> bf[2];
#pragma unroll
            for (int nt = 0; nt < 2; nt++)
                wmma::load_matrix_sync(bf[nt], Bh + k0 * LDBH + warp_n * 32 + nt * 16, LDBH);
#pragma unroll
            for (int mt = 0; mt < 4; mt++) {
                wmma::fragment<wmma::matrix_a, 16, 16, 16, __half, wmma::row_major> af;
                wmma::load_matrix_sync(af, Ah + (warp_m * 64 + mt * 16) * LDAH + k0, LDAH);
                wmma::mma_sync(acc[mt][0], af, bf[0], acc[mt][0]);
                wmma::mma_sync(acc[mt][1], af, bf[1], acc[mt][1]);
            }
        }
    }
    __syncthreads();   // all mma done before epilogue overwrites SMEM

    // ---- epilogue: accum -> SMEM (padded), then coalesced gmem stores with bias add ----
#pragma unroll
    for (int mt = 0; mt < 4; mt++)
#pragma unroll
        for (int nt = 0; nt < 2; nt++)
            wmma::store_matrix_sync(
                smf + (warp_m * 64 + mt * 16) * LDE + warp_n * 32 + nt * 16,
                acc[mt][nt], LDE, wmma::mem_row_major);
    __syncthreads();

    int c4 = tid & 31;                    // fixed float4 column per thread
    int rb = tid >> 5;                    // base row, stride 8
    float4 bv = *reinterpret_cast<const float4*>(bias + (size_t)n * OUT_F + ncol0 + c4 * 4);
#pragma unroll
    for (int i = 0; i < 16; i++) {
        int r = rb + i * 8;
        if (r < cnt) {
            float4 v = *reinterpret_cast<const float4*>(smf + r * LDE + c4 * 4);
            v.x += bv.x; v.y += bv.y; v.z += bv.z; v.w += bv.w;
            *reinterpret_cast<float4*>(out + (size_t)(row0 + r) * OUT_F + ncol0 + c4 * 4) = v;
        }
    }
}

// ---------------- launcher ----------------
extern "C" void kernel_launch(void* const* d_in, const int* in_sizes, int n_in,
                              void* d_out, int out_size) {
    const float* x      = (const float*)d_in[0];
    const float* weight = (const float*)d_in[1];
    const float* bias   = (const float*)d_in[2];
    const int*   net_id = (const int*)d_in[3];
    // d_in[4] = slot_id (unused: points are sorted, slots contiguous within segments)
    float* out = (float*)d_out;

    cudaFuncSetAttribute(grouped_gemm_kernel,
                         cudaFuncAttributeMaxDynamicSharedMemorySize, SMEM_TOTAL);

    seg_kernel<<<NPOINTS / 256, 256>>>(net_id);
    grouped_gemm_kernel<<<NNET * SUBTILES * NCOLS, THREADS, SMEM_TOTAL>>>(x, weight, bias, out);
}

// round 7
// speedup vs baseline: 2.7104x; 1.3720x over previous
#include <cuda_runtime.h>
#include <cuda_fp16.h>
#include <mma.h>
#include <cstdint>
#include <cstring>

using namespace nvcuda;

#define NPOINTS   262144
#define NNET      512
#define IN_F      256
#define OUT_F     256
#define BM        128
#define BN        128
#define BK        32
#define N_CHUNKS  (IN_F / BK)        /* 8 */
#define SUBTILES  6                  /* ceil(768/128) */
#define NCOLS     (OUT_F / BN)       /* 2 */
#define THREADS   256

// fp16 tile strides (halves), padded so LDSM phases spread banks
#define LDAH  40    /* 32 + 8 */
#define LDBH  136   /* 128 + 8 */
#define LDE   132   /* fp32 epilogue/bias stride */

// ---- dynamic SMEM layout (bytes) ----
#define AH_BYTES    (BM * LDAH * 2)              /* 10240 */
#define BH_BYTES    (BK * LDBH * 2)              /* 8704  */
#define TILE_STRIDE (AH_BYTES + BH_BYTES)        /* 18944, x2 buffers */
#define BIAS_OFF    (2 * TILE_STRIDE)            /* 37888 */
#define BIAS_BYTES  (16 * LDE * 4)               /* 8448  */
#define SMEM_TOTAL  (BIAS_OFF + BIAS_BYTES)      /* 46336; partial-epi (64*LDE*4=33792) overlays tiles */

__device__ int g_seg[NNET];   // start point index per network

// ---------------- helpers ----------------
__device__ __forceinline__ uint32_t h2u(__half2 h) {
    uint32_t u; memcpy(&u, &h, 4); return u;
}
__device__ __forceinline__ uint2 pack_f4(float4 v) {
    uint2 r;
    r.x = h2u(__float22half2_rn(make_float2(v.x, v.y)));
    r.y = h2u(__float22half2_rn(make_float2(v.z, v.w)));
    return r;
}

// ---------------- kernel 1: segment starts ----------------
__global__ void seg_kernel(const int* __restrict__ net_id) {
    int p = blockIdx.x * blockDim.x + threadIdx.x;
    if (p >= NPOINTS) return;
    int nid = net_id[p];
    if (p == 0 || net_id[p - 1] != nid) g_seg[nid] = p;
}

// -------- kernel 2: grouped GEMM (fp16 HMMA, reg-convert, direct epilogue) --------
__global__ void __launch_bounds__(THREADS, 2)
grouped_gemm_kernel(const float* __restrict__ x, const float* __restrict__ weight,
                    const float* __restrict__ bias, float* __restrict__ out) {
    int bx   = blockIdx.x;
    int ncol = bx & (NCOLS - 1);
    int sub  = (bx >> 1) % SUBTILES;
    int n    = bx / (SUBTILES * NCOLS);

    int s0 = g_seg[n];
    int s1 = (n == NNET - 1) ? NPOINTS : g_seg[n + 1];
    int row0 = s0 + sub * BM;
    int cnt = s1 - row0;
    if (cnt <= 0) return;                 // empty sub-tile: whole CTA exits
    if (cnt > BM) cnt = BM;
    int ncol0 = ncol * BN;

    extern __shared__ char smem[];
    float* smf = reinterpret_cast<float*>(smem);

    int tid = threadIdx.x;
    int wid = tid >> 5;
    int warp_m = wid >> 3;                // 0..? keep old mapping below
    warp_m = wid >> 2;                    // 0..1 -> 64-row slab
    int warp_n = wid & 3;                 // 0..3 -> 32-col slab

    const float* wsrc = weight + (size_t)n * IN_F * OUT_F;   // [in][out]: row-major KxN

    // per-thread load coordinates (fixed across chunks)
    int ar[4], ac[4]; bool av[4];
    int br[4], bc[4];
#pragma unroll
    for (int j = 0; j < 4; j++) {
        int idx = tid + j * THREADS;
        ar[j] = idx >> 3; ac[j] = idx & 7;      // A: 128 rows x 8 float4
        av[j] = ar[j] < cnt;
        br[j] = idx >> 5; bc[j] = idx & 31;     // B: 32 rows x 32 float4
    }

    // ---- bias replicated tile (16 rows x 128 cols fp32) ----
    {
        int rowb = tid >> 4, colb = (tid & 15) * 8;
        const float* bsrc = bias + (size_t)n * OUT_F + ncol0 + colb;
        float4 b0 = *reinterpret_cast<const float4*>(bsrc);
        float4 b1 = *reinterpret_cast<const float4*>(bsrc + 4);
        float* dst = smf + (BIAS_OFF / 4) + rowb * LDE + colb;
        *reinterpret_cast<float4*>(dst)     = b0;
        *reinterpret_cast<float4*>(dst + 4) = b1;
    }

    // ---- prefetch chunk 0 into fp16 registers ----
    uint2 pa[4], pb[4];
    {
        const float* xs = x + (size_t)row0 * IN_F;
        const float* ws = wsrc + ncol0;
#pragma unroll
        for (int j = 0; j < 4; j++) {
            float4 v = make_float4(0.f, 0.f, 0.f, 0.f);
            if (av[j]) v = *reinterpret_cast<const float4*>(xs + (size_t)ar[j] * IN_F + ac[j] * 4);
            pa[j] = pack_f4(v);
        }
#pragma unroll
        for (int j = 0; j < 4; j++) {
            float4 v = *reinterpret_cast<const float4*>(ws + (size_t)br[j] * OUT_F + bc[j] * 4);
            pb[j] = pack_f4(v);
        }
    }

    __syncthreads();   // bias tile ready

    // ---- accumulators preloaded with bias ----
    wmma::fragment<wmma::accumulator, 16, 16, 16, float> acc[4][2];
#pragma unroll
    for (int nt = 0; nt < 2; nt++) {
        wmma::load_matrix_sync(acc[0][nt],
                               smf + (BIAS_OFF / 4) + warp_n * 32 + nt * 16,
                               LDE, wmma::mem_row_major);
#pragma unroll
        for (int mt = 1; mt < 4; mt++) acc[mt][nt] = acc[0][nt];
    }

    // ---- mainloop: one __syncthreads per chunk, double-buffered fp16 tiles ----
    for (int c = 0; c < N_CHUNKS; c++) {
        int buf = c & 1;
        char* tbase = smem + buf * TILE_STRIDE;
        // STS current chunk's fp16 regs into tiles[buf]
#pragma unroll
        for (int j = 0; j < 4; j++)
            *reinterpret_cast<uint2*>(tbase + (ar[j] * LDAH + ac[j] * 4) * 2) = pa[j];
#pragma unroll
        for (int j = 0; j < 4; j++)
            *reinterpret_cast<uint2*>(tbase + AH_BYTES + (br[j] * LDBH + bc[j] * 4) * 2) = pb[j];
        __syncthreads();   // tiles[buf] ready; also orders mma(c-1) before next STS of buf^1

        // prefetch chunk c+1 (LDG issues here, hidden under mma below)
        if (c + 1 < N_CHUNKS) {
            int k0 = (c + 1) * BK;
            const float* xs = x + (size_t)row0 * IN_F + k0;
            const float* ws = wsrc + (size_t)k0 * OUT_F + ncol0;
#pragma unroll
            for (int j = 0; j < 4; j++) {
                float4 v = make_float4(0.f, 0.f, 0.f, 0.f);
                if (av[j]) v = *reinterpret_cast<const float4*>(xs + (size_t)ar[j] * IN_F + ac[j] * 4);
                pa[j] = pack_f4(v);
            }
#pragma unroll
            for (int j = 0; j < 4; j++) {
                float4 v = *reinterpret_cast<const float4*>(ws + (size_t)br[j] * OUT_F + bc[j] * 4);
                pb[j] = pack_f4(v);
            }
        }

        const __half* Ah = reinterpret_cast<const __half*>(smem + buf * TILE_STRIDE);
        const __half* Bh = reinterpret_cast<const __half*>(smem + buf * TILE_STRIDE + AH_BYTES);
#pragma unroll
        for (int ks = 0; ks < 2; ks++) {
            int k0 = ks * 16;
            wmma::fragment<wmma::matrix_b, 16, 16, 16, __half, wmma::row_major> bf[2];
#pragma unroll
            for (int nt = 0; nt < 2; nt++)
                wmma::load_matrix_sync(bf[nt], Bh + k0 * LDBH + warp_n * 32 + nt * 16, LDBH);
#pragma unroll
            for (int mt = 0; mt < 4; mt++) {
                wmma::fragment<wmma::matrix_a, 16, 16, 16, __half, wmma::row_major> af;
                wmma::load_matrix_sync(af, Ah + (warp_m * 64 + mt * 16) * LDAH + k0, LDAH);
                wmma::mma_sync(acc[mt][0], af, bf[0], acc[mt][0]);
                wmma::mma_sync(acc[mt][1], af, bf[1], acc[mt][1]);
            }
        }
    }

    // ---- epilogue (bias already in acc) ----
    if (cnt == BM) {
        // full tile: store fragments straight to gmem, no SMEM round-trip
#pragma unroll
        for (int mt = 0; mt < 4; mt++)
#pragma unroll
            for (int nt = 0; nt < 2; nt++)
                wmma::store_matrix_sync(
                    out + (size_t)(row0 + warp_m * 64 + mt * 16) * OUT_F
                        + ncol0 + warp_n * 32 + nt * 16,
                    acc[mt][nt], OUT_F, wmma::mem_row_major);
    } else {
        // partial tile: two 64-row half-passes through SMEM with row masking
        __syncthreads();   // all mma done before overwriting tiles region
        int c4 = tid & 31, rb = tid >> 5;
#pragma unroll
        for (int half = 0; half < 2; half++) {
            if (warp_m == half) {
#pragma unroll
                for (int mt = 0; mt < 4; mt++)
#pragma unroll
                    for (int nt = 0; nt < 2; nt++)
                        wmma::store_matrix_sync(
                            smf + (mt * 16) * LDE + warp_n * 32 + nt * 16,
                            acc[mt][nt], LDE, wmma::mem_row_major);
            }
            __syncthreads();
#pragma unroll
            for (int i = 0; i < 8; i++) {
                int rl = rb + i * 8;
                int r = half * 64 + rl;
                if (r < cnt)
                    *reinterpret_cast<float4*>(out + (size_t)(row0 + r) * OUT_F + ncol0 + c4 * 4) =
                        *reinterpret_cast<const float4*>(smf + rl * LDE + c4 * 4);
            }
            __syncthreads();
        }
    }
}

// ---------------- launcher ----------------
extern "C" void kernel_launch(void* const* d_in, const int* in_sizes, int n_in,
                              void* d_out, int out_size) {
    const float* x      = (const float*)d_in[0];
    const float* weight = (const float*)d_in[1];
    const float* bias   = (const float*)d_in[2];
    const int*   net_id = (const int*)d_in[3];
    // d_in[4] = slot_id (unused: points are sorted, slots contiguous within segments)
    float* out = (float*)d_out;

    cudaFuncSetAttribute(grouped_gemm_kernel,
                         cudaFuncAttributeMaxDynamicSharedMemorySize, SMEM_TOTAL);

    seg_kernel<<<NPOINTS / 256, 256>>>(net_id);
    grouped_gemm_kernel<<<NNET * SUBTILES * NCOLS, THREADS, SMEM_TOTAL>>>(x, weight, bias, out);
}